// round 13
// baseline (speedup 1.0000x reference)
#include <cuda_runtime.h>
#include <cuda_fp16.h>
#include <cstdint>

#define BB 16
#define LL 512
#define DD 256
#define FF 256
#define MM 2048
#define EPSV 1e-5f

// ---------------- device scratch ----------------
__device__ __align__(16) __half g_xh[BB * LL * DD];     // x in fp16
__device__ __align__(16) __half g_h1h[BB * LL * FF];    // conv1 output in fp16
// Winograd-transformed weights in mma-fragment order:
// uint4 idx = (ks*16 + p)*32 + lane;  ks = i*16 + kc (i = GEMM 0..3, kc = cin/16)
__device__ __align__(16) uint4 g_B1f[64 * 16 * 32];
__device__ __align__(16) uint4 g_B2f[64 * 16 * 32];
__device__ int g_cs[BB * LL];

// ---------------- helpers ----------------
__device__ __forceinline__ uint32_t smem_u32(const void* p) {
    uint32_t a;
    asm("{ .reg .u64 t; cvta.to.shared.u64 t, %1; cvt.u32.u64 %0, t; }"
        : "=r"(a) : "l"(p));
    return a;
}

__device__ __forceinline__ void cp16(uint32_t dst, const void* src, int valid) {
    int sz = valid ? 16 : 0;
    asm volatile("cp.async.cg.shared.global [%0], [%1], %2, %3;"
                 :: "r"(dst), "l"(src), "n"(16), "r"(sz));
}
__device__ __forceinline__ void cp_commit() {
    asm volatile("cp.async.commit_group;" ::: "memory");
}
__device__ __forceinline__ void cp_wait0() {
    asm volatile("cp.async.wait_group 0;" ::: "memory");
}

__device__ __forceinline__ void ldsm4(uint32_t* r, uint32_t addr) {
    asm volatile("ldmatrix.sync.aligned.m8n8.x4.shared.b16 {%0,%1,%2,%3}, [%4];"
                 : "=r"(r[0]), "=r"(r[1]), "=r"(r[2]), "=r"(r[3]) : "r"(addr));
}

__device__ __forceinline__ void ldg128(uint4& v, const uint4* p) {
    asm volatile("ld.global.nc.v4.u32 {%0,%1,%2,%3}, [%4];"
                 : "=r"(v.x), "=r"(v.y), "=r"(v.z), "=r"(v.w) : "l"(p));
}

__device__ __forceinline__ void mma16816(float* d, const uint32_t* a,
                                         const uint32_t* b) {
    asm volatile(
        "mma.sync.aligned.m16n8k16.row.col.f32.f16.f16.f32 "
        "{%0,%1,%2,%3}, {%4,%5,%6,%7}, {%8,%9}, {%0,%1,%2,%3};"
        : "+f"(d[0]), "+f"(d[1]), "+f"(d[2]), "+f"(d[3])
        : "r"(a[0]), "r"(a[1]), "r"(a[2]), "r"(a[3]), "r"(b[0]), "r"(b[1]));
}

// ---------------- prep: x -> fp16; weights -> Winograd fragment order ------
// G row i of F(2,3): {g0, (g0+g1+g2)/2, (g0-g1+g2)/2, g2}
__global__ void prep_convert(const float* __restrict__ x,
                             const float* __restrict__ w1,
                             const float* __restrict__ w2) {
    int i4 = blockIdx.x * 256 + threadIdx.x;   // vec4 index
    if (i4 < BB * LL * DD / 4) {
        float4 v = reinterpret_cast<const float4*>(x)[i4];
        __half h[4];
        h[0] = __float2half(v.x);
        h[1] = __float2half(v.y);
        h[2] = __float2half(v.z);
        h[3] = __float2half(v.w);
        reinterpret_cast<uint2*>(g_xh)[i4] = *(uint2*)h;
    }
    if (i4 < 64 * 16 * 32) {
        int lane = i4 & 31;
        int rest = i4 >> 5;
        int p = rest & 15;
        int ks = rest >> 4;          // 0..63
        int gi = ks >> 4;            // GEMM index 0..3
        int kc = ks & 15;
        int c0 = kc * 16 + (lane & 3) * 2;
        int na = p * 16 + (lane >> 2), nb = na + 8;
        auto G = [&](const float* w, int n, int c) -> float {
            float g0 = w[n * 768 + c * 3 + 0];
            float g1 = w[n * 768 + c * 3 + 1];
            float g2 = w[n * 768 + c * 3 + 2];
            if (gi == 0) return g0;
            if (gi == 1) return 0.5f * (g0 + g1 + g2);
            if (gi == 2) return 0.5f * (g0 - g1 + g2);
            return g2;
        };
        auto pk = [&](const float* w, int n, int c) -> unsigned {
            __half2 h = __floats2half2_rn(G(w, n, c), G(w, n, c + 1));
            return *(unsigned*)&h;
        };
        uint4 v1, v2;
        v1.x = pk(w1, na, c0);
        v1.y = pk(w1, na, c0 + 8);
        v1.z = pk(w1, nb, c0);
        v1.w = pk(w1, nb, c0 + 8);
        v2.x = pk(w2, na, c0);
        v2.y = pk(w2, na, c0 + 8);
        v2.z = pk(w2, nb, c0);
        v2.w = pk(w2, nb, c0 + 8);
        g_B1f[i4] = v1;
        g_B2f[i4] = v2;
    }
}

// ---------------- cumsum ----------------
__global__ void cumsum_k(const int* __restrict__ t, int* __restrict__ cs) {
    __shared__ int s[LL];
    int b = blockIdx.x, tid = threadIdx.x;
    s[tid] = t[(b << 9) + tid];
    __syncthreads();
    for (int off = 1; off < LL; off <<= 1) {
        int v = (tid >= off) ? s[tid - off] : 0;
        __syncthreads();
        s[tid] += v;
        __syncthreads();
    }
    cs[(b << 9) + tid] = s[tid];
}

// ---------------- length regulate (exact) ----------------
__global__ void regulate(const float* __restrict__ x,
                         const int* __restrict__ cs,
                         float* __restrict__ out) {
    int warp = threadIdx.x >> 5, lane = threadIdx.x & 31;
    int gm = blockIdx.x * 8 + warp;
    int b = gm >> 11;
    int m = gm & (MM - 1);
    const int* c = cs + (b << 9);
    int total = c[LL - 1];
    float4* dst = reinterpret_cast<float4*>(out) + (size_t)gm * 64;
    if (m < total) {
        int lo = 0, hi = LL - 1;
        while (lo < hi) {
            int mid = (lo + hi) >> 1;
            if (c[mid] > m) hi = mid; else lo = mid + 1;
        }
        const float4* src =
            reinterpret_cast<const float4*>(x) + ((size_t)((b << 9) + lo)) * 64;
        dst[lane] = src[lane];
        dst[lane + 32] = src[lane + 32];
    } else {
        float4 z = make_float4(0.f, 0.f, 0.f, 0.f);
        dst[lane] = z;
        dst[lane + 32] = z;
    }
}

// ---------------- Winograd F(2,3) conv + bias + LN + ReLU (+linear) --------
// CTA: 64 output rows = 32 tiles x 256 ch; 16 warps (2m x 8n), warp 16tile x 32ch.
// Halo (66x256 fp16) -> smem; in-smem input transform -> 4 D tiles (32x256);
// 4 GEMMs K=256 (64 k-steps), B via LDG-fragment ring; fold after each GEMM.
#define S_PAR   0                  // bias/g/be/lw: 4 x 1KB
#define S_A     4096
#define A_STR   528
#define S_D     (4096 + 66 * A_STR)        // 38944
#define D_TSZ   (32 * A_STR)               // 16896 per D tile
#define S_TOTAL (S_D + 4 * D_TSZ)          // 106528 (stats reuse S_D)

__global__ void __launch_bounds__(512, 1)
conv_mma(const __half* __restrict__ a_in,
         const uint4* __restrict__ Bf,
         const float* __restrict__ bias,
         const float* __restrict__ gamma,
         const float* __restrict__ beta,
         int mode,
         __half* __restrict__ out_h,
         const float* __restrict__ lw,
         const float* __restrict__ lb,
         float* __restrict__ dup) {
    extern __shared__ char sm[];
    const uint32_t sb = smem_u32(sm);
    const int tid = threadIdx.x;
    const int lane = tid & 31;
    const int wid = tid >> 5;
    const int wm = wid & 1;          // tile-m half: tiles wm*16..+15
    const int wn = wid >> 1;         // n eighth: ch wn*32..+31
    const int row0 = blockIdx.x * 64;
    const int l0 = row0 & 511;

    float* s_bias = (float*)(sm + S_PAR);
    float* s_g = (float*)(sm + S_PAR + 1024);
    float* s_be = (float*)(sm + S_PAR + 2048);
    float* s_lw = (float*)(sm + S_PAR + 3072);
    if (tid < 256) {
        s_bias[tid] = bias[tid];
        s_g[tid] = gamma[tid];
        s_be[tid] = beta[tid];
        s_lw[tid] = (mode == 1) ? lw[tid] : 0.f;
    }

    // halo tile (66 rows x 512B) via cp.async
    for (int idx = tid; idx < 66 * 32; idx += 512) {
        int r = idx >> 5, c = idx & 31;
        int l = l0 - 1 + r;
        int v = ((unsigned)l < 512u) ? 1 : 0;
        long grow = (long)row0 - 1 + r;
        const __half* src = a_in + (v ? (grow * 256 + c * 8) : 0);
        cp16(sb + S_A + (uint32_t)(r * A_STR + c * 16), src, v);
    }
    cp_commit();

    // per-warp B fragment pointer: idx4 = (ks*16 + wn*2 + g)*32 + lane
    const uint4* Bw = Bf + (size_t)(wn * 2) * 32 + lane;

    // B prefetch ring (3 slots x 2 uint4, distance 2) — overlaps transform
    uint4 bS[3][2];
#pragma unroll
    for (int g = 0; g < 2; g++) ldg128(bS[0][g], Bw + g * 32);
#pragma unroll
    for (int g = 0; g < 2; g++) ldg128(bS[1][g], Bw + 512 + g * 32);

    cp_wait0();
    __syncthreads();

    // -------- input transform: halo -> 4 D tiles (half2 ops) --------
    {
        const __half2* halo = (const __half2*)(sm + S_A);
        __half2* D0 = (__half2*)(sm + S_D);
        __half2* D1 = (__half2*)(sm + S_D + D_TSZ);
        __half2* D2 = (__half2*)(sm + S_D + 2 * D_TSZ);
        __half2* D3 = (__half2*)(sm + S_D + 3 * D_TSZ);
        const int hs = A_STR / 4;   // half2 row stride = 132
#pragma unroll
        for (int it = 0; it < 8; it++) {
            int idx = it * 512 + tid;        // 0..4095
            int t = idx >> 7, c2 = idx & 127;
            __half2 a0 = halo[(2 * t) * hs + c2];
            __half2 a1 = halo[(2 * t + 1) * hs + c2];
            __half2 a2 = halo[(2 * t + 2) * hs + c2];
            __half2 a3 = halo[(2 * t + 3) * hs + c2];
            D0[t * hs + c2] = __hsub2(a0, a2);
            D1[t * hs + c2] = __hadd2(a1, a2);
            D2[t * hs + c2] = __hsub2(a2, a1);
            D3[t * hs + c2] = __hsub2(a1, a3);
        }
    }
    __syncthreads();

    // per-lane A ldsm base (within a D tile)
    const uint32_t aL = sb + S_D +
        (uint32_t)((wm * 16 + (lane & 15)) * A_STR + (lane >> 4) * 16);

    float y0[4][4], y1[4][4], cur[4][4];
#pragma unroll
    for (int nt = 0; nt < 4; nt++)
#pragma unroll
        for (int j = 0; j < 4; j++) {
            y0[nt][j] = 0.f;
            y1[nt][j] = 0.f;
            cur[nt][j] = 0.f;
        }

    uint32_t aF[2][4];
    ldsm4(aF[0], aL);     // ks = 0: GEMM 0, kc 0

#pragma unroll
    for (int gi = 0; gi < 4; gi++) {
#pragma unroll
        for (int kc = 0; kc < 16; kc++) {
            const int ks = gi * 16 + kc;
            // B prefetch ks+2
            if (ks + 2 < 64) {
                const uint4* bp = Bw + (size_t)(ks + 2) * 512;
#pragma unroll
                for (int g = 0; g < 2; g++)
                    ldg128(bS[(ks + 2) % 3][g], bp + g * 32);
            }
            // A prefetch ks+1
            if (ks + 1 < 64) {
                const int gn = (ks + 1) >> 4, kn = (ks + 1) & 15;
                ldsm4(aF[(ks + 1) & 1],
                      aL + (uint32_t)(gn * D_TSZ + kn * 32));
            }
            // 4 HMMA
            const int sl = ks % 3, ca = ks & 1;
#pragma unroll
            for (int g = 0; g < 2; g++) {
                const uint32_t* bb = (const uint32_t*)&bS[sl][g];
                mma16816(cur[2 * g], aF[ca], bb);
                mma16816(cur[2 * g + 1], aF[ca], bb + 2);
            }
        }
        // fold GEMM gi into y0/y1:  y0 = m0+m1+m2,  y1 = m1-m2-m3
#pragma unroll
        for (int nt = 0; nt < 4; nt++)
#pragma unroll
            for (int j = 0; j < 4; j++) {
                float c = cur[nt][j];
                if (gi == 0) { y0[nt][j] += c; }
                else if (gi == 1) { y0[nt][j] += c; y1[nt][j] += c; }
                else if (gi == 2) { y0[nt][j] += c; y1[nt][j] -= c; }
                else { y1[nt][j] -= c; }
                cur[nt][j] = 0.f;
            }
    }

    __syncthreads();   // D region about to be reused as stats

    // -------- epilogue: output transform rows (2t, 2t+1) -> stats, LN ------
    float* stats = (float*)(sm + S_D);       // 64 x 264 fp32
#pragma unroll
    for (int nt = 0; nt < 4; nt++) {
        int n = wn * 32 + nt * 8 + (lane & 3) * 2;
        int t = wm * 16 + (lane >> 2);
        float b0 = s_bias[n], b1 = s_bias[n + 1];
        stats[(2 * t) * 264 + n] = y0[nt][0] + b0;
        stats[(2 * t) * 264 + n + 1] = y0[nt][1] + b1;
        stats[(2 * t + 1) * 264 + n] = y1[nt][0] + b0;
        stats[(2 * t + 1) * 264 + n + 1] = y1[nt][1] + b1;
        int t2 = t + 8;
        stats[(2 * t2) * 264 + n] = y0[nt][2] + b0;
        stats[(2 * t2) * 264 + n + 1] = y0[nt][3] + b1;
        stats[(2 * t2 + 1) * 264 + n] = y1[nt][2] + b0;
        stats[(2 * t2 + 1) * 264 + n + 1] = y1[nt][3] + b1;
    }
    __syncthreads();

    // 8 threads per row
    const int row = tid >> 3, q = tid & 7;
    const float* rp = stats + row * 264 + q * 32;
    float sum = 0.f, ssq = 0.f;
#pragma unroll
    for (int i = 0; i < 32; i++) {
        float v = rp[i];
        sum += v;
        ssq = fmaf(v, v, ssq);
    }
#pragma unroll
    for (int o = 1; o < 8; o <<= 1) {
        sum += __shfl_xor_sync(0xffffffffu, sum, o);
        ssq += __shfl_xor_sync(0xffffffffu, ssq, o);
    }
    float mu = sum * (1.f / 256.f);
    float rs = rsqrtf(ssq * (1.f / 256.f) - mu * mu + EPSV);

    if (mode == 1) {
        float dot = 0.f;
#pragma unroll
        for (int i = 0; i < 32; i++) {
            int c = q * 32 + i;
            float y = fmaxf((rp[i] - mu) * rs * s_g[c] + s_be[c], 0.f);
            dot = fmaf(y, s_lw[c], dot);
        }
#pragma unroll
        for (int o = 1; o < 8; o <<= 1)
            dot += __shfl_xor_sync(0xffffffffu, dot, o);
        if (q == 0) dup[row0 + row] = fmaxf(dot + lb[0], 0.f);
    } else {
#pragma unroll
        for (int v8 = 0; v8 < 4; v8++) {
            __half h[8];
#pragma unroll
            for (int j = 0; j < 8; j++) {
                int c = q * 32 + v8 * 8 + j;
                float y = fmaxf((rp[v8 * 8 + j] - mu) * rs * s_g[c] + s_be[c], 0.f);
                h[j] = __float2half(y);
            }
            size_t go = (size_t)(row0 + row) * 256 + q * 32 + v8 * 8;
            *(uint4*)(out_h + go) = *(uint4*)h;
        }
    }
}

// ---------------------------------------------------------------------------
extern "C" void kernel_launch(void* const* d_in, const int* in_sizes, int n_in,
                              void* d_out, int out_size) {
    const float* x      = (const float*)d_in[0];
    const int*   target = (const int*)d_in[1];
    const float* w1  = (const float*)d_in[3];
    const float* b1  = (const float*)d_in[4];
    const float* g1  = (const float*)d_in[5];
    const float* be1 = (const float*)d_in[6];
    const float* w2  = (const float*)d_in[7];
    const float* b2  = (const float*)d_in[8];
    const float* g2  = (const float*)d_in[9];
    const float* be2 = (const float*)d_in[10];
    const float* lw  = (const float*)d_in[11];
    const float* lb  = (const float*)d_in[12];

    float* out = (float*)d_out;
    float* dup = out + (size_t)BB * MM * DD;

    __half *xh, *h1h;
    uint4 *B1f, *B2f;
    int* cs;
    cudaGetSymbolAddress((void**)&xh, g_xh);
    cudaGetSymbolAddress((void**)&h1h, g_h1h);
    cudaGetSymbolAddress((void**)&B1f, g_B1f);
    cudaGetSymbolAddress((void**)&B2f, g_B2f);
    cudaGetSymbolAddress((void**)&cs, g_cs);

    cudaFuncSetAttribute((const void*)conv_mma,
                         cudaFuncAttributeMaxDynamicSharedMemorySize, S_TOTAL);

    prep_convert<<<(BB * LL * DD / 4 + 255) / 256, 256>>>(x, w1, w2);
    cumsum_k<<<BB, LL>>>(target, cs);
    regulate<<<BB * MM / 8, 256>>>(x, cs, out);

    conv_mma<<<BB * LL / 64, 512, S_TOTAL>>>(xh, B1f, b1, g1, be1, 0,
                                             h1h, lw, lb, dup);
    conv_mma<<<BB * LL / 64, 512, S_TOTAL>>>(h1h, B2f, b2, g2, be2, 1,
                                             h1h, lw, lb, dup);
}

// round 14
// speedup vs baseline: 1.0882x; 1.0882x over previous
#include <cuda_runtime.h>
#include <cuda_fp16.h>
#include <cstdint>

#define BB 16
#define LL 512
#define DD 256
#define FF 256
#define MM 2048
#define EPSV 1e-5f

// ---------------- device scratch ----------------
__device__ __align__(16) __half g_xh[BB * LL * DD];     // x in fp16
__device__ __align__(16) __half g_h1h[BB * LL * FF];    // conv1 output in fp16
// Winograd-transformed weights in mma-fragment order:
// uint4 idx = (ks*16 + p)*32 + lane;  ks = i*16 + kc (i = GEMM 0..3, kc = cin/16)
__device__ __align__(16) uint4 g_B1f[64 * 16 * 32];
__device__ __align__(16) uint4 g_B2f[64 * 16 * 32];
__device__ int g_cs[BB * LL];

// ---------------- helpers ----------------
__device__ __forceinline__ uint32_t smem_u32(const void* p) {
    uint32_t a;
    asm("{ .reg .u64 t; cvta.to.shared.u64 t, %1; cvt.u32.u64 %0, t; }"
        : "=r"(a) : "l"(p));
    return a;
}

__device__ __forceinline__ void cp16(uint32_t dst, const void* src, int valid) {
    int sz = valid ? 16 : 0;
    asm volatile("cp.async.cg.shared.global [%0], [%1], %2, %3;"
                 :: "r"(dst), "l"(src), "n"(16), "r"(sz));
}
__device__ __forceinline__ void cp_commit() {
    asm volatile("cp.async.commit_group;" ::: "memory");
}
__device__ __forceinline__ void cp_wait0() {
    asm volatile("cp.async.wait_group 0;" ::: "memory");
}

__device__ __forceinline__ void ldsm4(uint32_t* r, uint32_t addr) {
    asm volatile("ldmatrix.sync.aligned.m8n8.x4.shared.b16 {%0,%1,%2,%3}, [%4];"
                 : "=r"(r[0]), "=r"(r[1]), "=r"(r[2]), "=r"(r[3]) : "r"(addr));
}

__device__ __forceinline__ void ldg128(uint4& v, const uint4* p) {
    asm volatile("ld.global.nc.v4.u32 {%0,%1,%2,%3}, [%4];"
                 : "=r"(v.x), "=r"(v.y), "=r"(v.z), "=r"(v.w) : "l"(p));
}

__device__ __forceinline__ void mma16816(float* d, const uint32_t* a,
                                         const uint32_t* b) {
    asm volatile(
        "mma.sync.aligned.m16n8k16.row.col.f32.f16.f16.f32 "
        "{%0,%1,%2,%3}, {%4,%5,%6,%7}, {%8,%9}, {%0,%1,%2,%3};"
        : "+f"(d[0]), "+f"(d[1]), "+f"(d[2]), "+f"(d[3])
        : "r"(a[0]), "r"(a[1]), "r"(a[2]), "r"(a[3]), "r"(b[0]), "r"(b[1]));
}

// ---------------- prep: x -> fp16; weights -> Winograd fragment order ------
// G row i of F(2,3): {g0, (g0+g1+g2)/2, (g0-g1+g2)/2, g2}
__global__ void prep_convert(const float* __restrict__ x,
                             const float* __restrict__ w1,
                             const float* __restrict__ w2) {
    int i4 = blockIdx.x * 256 + threadIdx.x;   // vec4 index
    if (i4 < BB * LL * DD / 4) {
        float4 v = reinterpret_cast<const float4*>(x)[i4];
        __half h[4];
        h[0] = __float2half(v.x);
        h[1] = __float2half(v.y);
        h[2] = __float2half(v.z);
        h[3] = __float2half(v.w);
        reinterpret_cast<uint2*>(g_xh)[i4] = *(uint2*)h;
    }
    if (i4 < 64 * 16 * 32) {
        int lane = i4 & 31;
        int rest = i4 >> 5;
        int p = rest & 15;
        int ks = rest >> 4;          // 0..63
        int gi = ks >> 4;            // GEMM index 0..3
        int kc = ks & 15;
        int c0 = kc * 16 + (lane & 3) * 2;
        int na = p * 16 + (lane >> 2), nb = na + 8;
        auto G = [&](const float* w, int n, int c) -> float {
            float g0 = w[n * 768 + c * 3 + 0];
            float g1 = w[n * 768 + c * 3 + 1];
            float g2 = w[n * 768 + c * 3 + 2];
            if (gi == 0) return g0;
            if (gi == 1) return 0.5f * (g0 + g1 + g2);
            if (gi == 2) return 0.5f * (g0 - g1 + g2);
            return g2;
        };
        auto pk = [&](const float* w, int n, int c) -> unsigned {
            __half2 h = __floats2half2_rn(G(w, n, c), G(w, n, c + 1));
            return *(unsigned*)&h;
        };
        uint4 v1, v2;
        v1.x = pk(w1, na, c0);
        v1.y = pk(w1, na, c0 + 8);
        v1.z = pk(w1, nb, c0);
        v1.w = pk(w1, nb, c0 + 8);
        v2.x = pk(w2, na, c0);
        v2.y = pk(w2, na, c0 + 8);
        v2.z = pk(w2, nb, c0);
        v2.w = pk(w2, nb, c0 + 8);
        g_B1f[i4] = v1;
        g_B2f[i4] = v2;
    }
}

// ---------------- cumsum ----------------
__global__ void cumsum_k(const int* __restrict__ t, int* __restrict__ cs) {
    __shared__ int s[LL];
    int b = blockIdx.x, tid = threadIdx.x;
    s[tid] = t[(b << 9) + tid];
    __syncthreads();
    for (int off = 1; off < LL; off <<= 1) {
        int v = (tid >= off) ? s[tid - off] : 0;
        __syncthreads();
        s[tid] += v;
        __syncthreads();
    }
    cs[(b << 9) + tid] = s[tid];
}

// ---------------- length regulate (exact) ----------------
__global__ void regulate(const float* __restrict__ x,
                         const int* __restrict__ cs,
                         float* __restrict__ out) {
    int warp = threadIdx.x >> 5, lane = threadIdx.x & 31;
    int gm = blockIdx.x * 8 + warp;
    int b = gm >> 11;
    int m = gm & (MM - 1);
    const int* c = cs + (b << 9);
    int total = c[LL - 1];
    float4* dst = reinterpret_cast<float4*>(out) + (size_t)gm * 64;
    if (m < total) {
        int lo = 0, hi = LL - 1;
        while (lo < hi) {
            int mid = (lo + hi) >> 1;
            if (c[mid] > m) hi = mid; else lo = mid + 1;
        }
        const float4* src =
            reinterpret_cast<const float4*>(x) + ((size_t)((b << 9) + lo)) * 64;
        dst[lane] = src[lane];
        dst[lane + 32] = src[lane + 32];
    } else {
        float4 z = make_float4(0.f, 0.f, 0.f, 0.f);
        dst[lane] = z;
        dst[lane + 32] = z;
    }
}

// ---------------- Winograd F(2,3) conv + bias + LN + ReLU (+linear) --------
// CTA: 64 output rows = 32 tiles x 256 ch; 16 warps (2m x 8n), warp 16tile x 32ch.
#define S_PAR   0                  // bias/g/be/lw: 4 x 1KB
#define S_A     4096
#define A_STR   528
#define S_D     (4096 + 66 * A_STR)        // 38944
#define D_TSZ   (32 * A_STR)               // 16896 per D tile
#define S_TOTAL (S_D + 4 * D_TSZ)          // 106528 (stats reuse S_D)

__global__ void __launch_bounds__(512, 1)
conv_mma(const __half* __restrict__ a_in,
         const uint4* __restrict__ Bf,
         const float* __restrict__ bias,
         const float* __restrict__ gamma,
         const float* __restrict__ beta,
         int mode,
         __half* __restrict__ out_h,
         const float* __restrict__ lw,
         const float* __restrict__ lb,
         float* __restrict__ dup) {
    extern __shared__ char sm[];
    const uint32_t sb = smem_u32(sm);
    const int tid = threadIdx.x;
    const int lane = tid & 31;
    const int wid = tid >> 5;
    const int wm = wid & 1;          // tile-m half: tiles wm*16..+15
    const int wn = wid >> 1;         // n eighth: ch wn*32..+31
    const int row0 = blockIdx.x * 64;
    const int l0 = row0 & 511;

    float* s_bias = (float*)(sm + S_PAR);
    float* s_g = (float*)(sm + S_PAR + 1024);
    float* s_be = (float*)(sm + S_PAR + 2048);
    float* s_lw = (float*)(sm + S_PAR + 3072);
    if (tid < 256) {
        s_bias[tid] = bias[tid];
        s_g[tid] = gamma[tid];
        s_be[tid] = beta[tid];
        s_lw[tid] = (mode == 1) ? lw[tid] : 0.f;
    }

    // halo tile (66 rows x 512B) via cp.async
    for (int idx = tid; idx < 66 * 32; idx += 512) {
        int r = idx >> 5, c = idx & 31;
        int l = l0 - 1 + r;
        int v = ((unsigned)l < 512u) ? 1 : 0;
        long grow = (long)row0 - 1 + r;
        const __half* src = a_in + (v ? (grow * 256 + c * 8) : 0);
        cp16(sb + S_A + (uint32_t)(r * A_STR + c * 16), src, v);
    }
    cp_commit();

    // per-warp B fragment pointer: idx4 = (ks*16 + wn*2 + g)*32 + lane
    const uint4* Bw = Bf + (size_t)(wn * 2) * 32 + lane;

    // B prefetch ring (3 slots x 2 uint4, distance 2)
    uint4 bS[3][2];
#pragma unroll
    for (int g = 0; g < 2; g++) ldg128(bS[0][g], Bw + g * 32);
#pragma unroll
    for (int g = 0; g < 2; g++) ldg128(bS[1][g], Bw + 512 + g * 32);

    cp_wait0();
    __syncthreads();

    // -------- input transform: halo -> 4 D tiles (half2 ops) --------
    {
        const __half2* halo = (const __half2*)(sm + S_A);
        __half2* D0 = (__half2*)(sm + S_D);
        __half2* D1 = (__half2*)(sm + S_D + D_TSZ);
        __half2* D2 = (__half2*)(sm + S_D + 2 * D_TSZ);
        __half2* D3 = (__half2*)(sm + S_D + 3 * D_TSZ);
        const int hs = A_STR / 4;   // half2 row stride = 132
#pragma unroll
        for (int it = 0; it < 8; it++) {
            int idx = it * 512 + tid;        // 0..4095
            int t = idx >> 7, c2 = idx & 127;
            __half2 a0 = halo[(2 * t) * hs + c2];
            __half2 a1 = halo[(2 * t + 1) * hs + c2];
            __half2 a2 = halo[(2 * t + 2) * hs + c2];
            __half2 a3 = halo[(2 * t + 3) * hs + c2];
            D0[t * hs + c2] = __hsub2(a0, a2);
            D1[t * hs + c2] = __hadd2(a1, a2);
            D2[t * hs + c2] = __hsub2(a2, a1);
            D3[t * hs + c2] = __hsub2(a1, a3);
        }
    }
    __syncthreads();

    // per-lane A ldsm base (within a D tile)
    const uint32_t aL = sb + S_D +
        (uint32_t)((wm * 16 + (lane & 15)) * A_STR + (lane >> 4) * 16);

    float y0[4][4], y1[4][4], cur[4][4];
#pragma unroll
    for (int nt = 0; nt < 4; nt++)
#pragma unroll
        for (int j = 0; j < 4; j++) {
            y0[nt][j] = 0.f;
            y1[nt][j] = 0.f;
            cur[nt][j] = 0.f;
        }

    uint32_t aF[2][4];
    ldsm4(aF[0], aL);     // ks = 0: GEMM 0, kc 0

#pragma unroll
    for (int gi = 0; gi < 4; gi++) {
#pragma unroll
        for (int kc = 0; kc < 16; kc++) {
            const int ks = gi * 16 + kc;
            if (ks + 2 < 64) {
                const uint4* bp = Bw + (size_t)(ks + 2) * 512;
#pragma unroll
                for (int g = 0; g < 2; g++)
                    ldg128(bS[(ks + 2) % 3][g], bp + g * 32);
            }
            if (ks + 1 < 64) {
                const int gn = (ks + 1) >> 4, kn = (ks + 1) & 15;
                ldsm4(aF[(ks + 1) & 1],
                      aL + (uint32_t)(gn * D_TSZ + kn * 32));
            }
            const int sl = ks % 3, ca = ks & 1;
#pragma unroll
            for (int g = 0; g < 2; g++) {
                const uint32_t* bb = (const uint32_t*)&bS[sl][g];
                mma16816(cur[2 * g], aF[ca], bb);
                mma16816(cur[2 * g + 1], aF[ca], bb + 2);
            }
        }
        // fold GEMM gi:  y0 = m0+m1+m2,  y1 = m1-m2-m3
#pragma unroll
        for (int nt = 0; nt < 4; nt++)
#pragma unroll
            for (int j = 0; j < 4; j++) {
                float c = cur[nt][j];
                if (gi == 0) { y0[nt][j] += c; }
                else if (gi == 1) { y0[nt][j] += c; y1[nt][j] += c; }
                else if (gi == 2) { y0[nt][j] += c; y1[nt][j] -= c; }
                else { y1[nt][j] -= c; }
                cur[nt][j] = 0.f;
            }
    }

    __syncthreads();   // D region about to be reused as stats

    // -------- epilogue --------
    float* stats = (float*)(sm + S_D);       // 64 x 264 fp32
#pragma unroll
    for (int nt = 0; nt < 4; nt++) {
        int n = wn * 32 + nt * 8 + (lane & 3) * 2;
        int t = wm * 16 + (lane >> 2);
        float b0 = s_bias[n], b1 = s_bias[n + 1];
        stats[(2 * t) * 264 + n] = y0[nt][0] + b0;
        stats[(2 * t) * 264 + n + 1] = y0[nt][1] + b1;
        stats[(2 * t + 1) * 264 + n] = y1[nt][0] + b0;
        stats[(2 * t + 1) * 264 + n + 1] = y1[nt][1] + b1;
        int t2 = t + 8;
        stats[(2 * t2) * 264 + n] = y0[nt][2] + b0;
        stats[(2 * t2) * 264 + n + 1] = y0[nt][3] + b1;
        stats[(2 * t2 + 1) * 264 + n] = y1[nt][2] + b0;
        stats[(2 * t2 + 1) * 264 + n + 1] = y1[nt][3] + b1;
    }
    __syncthreads();

    const int row = tid >> 3, q = tid & 7;
    const float* rp = stats + row * 264 + q * 32;
    float sum = 0.f, ssq = 0.f;
#pragma unroll
    for (int i = 0; i < 32; i++) {
        float v = rp[i];
        sum += v;
        ssq = fmaf(v, v, ssq);
    }
#pragma unroll
    for (int o = 1; o < 8; o <<= 1) {
        sum += __shfl_xor_sync(0xffffffffu, sum, o);
        ssq += __shfl_xor_sync(0xffffffffu, ssq, o);
    }
    float mu = sum * (1.f / 256.f);
    float rs = rsqrtf(ssq * (1.f / 256.f) - mu * mu + EPSV);

    if (mode == 1) {
        float dot = 0.f;
#pragma unroll
        for (int i = 0; i < 32; i++) {
            int c = q * 32 + i;
            float y = fmaxf((rp[i] - mu) * rs * s_g[c] + s_be[c], 0.f);
            dot = fmaf(y, s_lw[c], dot);
        }
#pragma unroll
        for (int o = 1; o < 8; o <<= 1)
            dot += __shfl_xor_sync(0xffffffffu, dot, o);
        if (q == 0) dup[row0 + row] = fmaxf(dot + lb[0], 0.f);
    } else {
#pragma unroll
        for (int v8 = 0; v8 < 4; v8++) {
            __half h[8];
#pragma unroll
            for (int j = 0; j < 8; j++) {
                int c = q * 32 + v8 * 8 + j;
                float y = fmaxf((rp[v8 * 8 + j] - mu) * rs * s_g[c] + s_be[c], 0.f);
                h[j] = __float2half(y);
            }
            size_t go = (size_t)(row0 + row) * 256 + q * 32 + v8 * 8;
            *(uint4*)(out_h + go) = *(uint4*)h;
        }
    }
}

// ---------------------------------------------------------------------------
extern "C" void kernel_launch(void* const* d_in, const int* in_sizes, int n_in,
                              void* d_out, int out_size) {
    const float* x      = (const float*)d_in[0];
    const int*   target = (const int*)d_in[1];
    const float* w1  = (const float*)d_in[3];
    const float* b1  = (const float*)d_in[4];
    const float* g1  = (const float*)d_in[5];
    const float* be1 = (const float*)d_in[6];
    const float* w2  = (const float*)d_in[7];
    const float* b2  = (const float*)d_in[8];
    const float* g2  = (const float*)d_in[9];
    const float* be2 = (const float*)d_in[10];
    const float* lw  = (const float*)d_in[11];
    const float* lb  = (const float*)d_in[12];

    float* out = (float*)d_out;
    float* dup = out + (size_t)BB * MM * DD;

    __half *xh, *h1h;
    uint4 *B1f, *B2f;
    int* cs;
    cudaGetSymbolAddress((void**)&xh, g_xh);
    cudaGetSymbolAddress((void**)&h1h, g_h1h);
    cudaGetSymbolAddress((void**)&B1f, g_B1f);
    cudaGetSymbolAddress((void**)&B2f, g_B2f);
    cudaGetSymbolAddress((void**)&cs, g_cs);

    cudaFuncSetAttribute((const void*)conv_mma,
                         cudaFuncAttributeMaxDynamicSharedMemorySize, S_TOTAL);

    // lazy persistent stream + events (created on the uncaptured correctness
    // call; reused identically on the capture call — no allocation of device
    // memory, fork/join via events is graph-capturable)
    static cudaStream_t s2 = nullptr;
    static cudaEvent_t eFork = nullptr, eJoin = nullptr;
    if (!s2) {
        cudaStreamCreateWithFlags(&s2, cudaStreamNonBlocking);
        cudaEventCreateWithFlags(&eFork, cudaEventDisableTiming);
        cudaEventCreateWithFlags(&eJoin, cudaEventDisableTiming);
    }

    // fork: side chain (cumsum -> regulate) runs concurrently with
    // prep -> conv1 on the main stream
    cudaEventRecord(eFork, 0);
    cudaStreamWaitEvent(s2, eFork, 0);

    cumsum_k<<<BB, LL, 0, s2>>>(target, cs);
    regulate<<<BB * MM / 8, 256, 0, s2>>>(x, cs, out);
    cudaEventRecord(eJoin, s2);

    prep_convert<<<(BB * LL * DD / 4 + 255) / 256, 256>>>(x, w1, w2);
    conv_mma<<<BB * LL / 64, 512, S_TOTAL>>>(xh, B1f, b1, g1, be1, 0,
                                             h1h, lw, lb, dup);
    conv_mma<<<BB * LL / 64, 512, S_TOTAL>>>(h1h, B2f, b2, g2, be2, 1,
                                             h1h, lw, lb, dup);

    // join
    cudaStreamWaitEvent(0, eJoin, 0);
}